// round 16
// baseline (speedup 1.0000x reference)
#include <cuda_runtime.h>
#include <cstdint>

#define HH 448
#define WW 512
#define HW (HH*WW)        // 229376
#define CHW 65536         // per-h plane: 128*512 ([c][w]) or 512*128 ([w][c])

typedef unsigned long long ull;

// scratch (allocation-free rule)
__device__ float g_t1[(size_t)HH*CHW];      // [h][c][w]
__device__ float g_t2[(size_t)HH*CHW];      // [h][c][w]
__device__ float g_xr[(size_t)HH*CHW];      // TRANSPOSED: [h][w][c]
__device__ int   g_inds[HW];

__device__ __forceinline__ void fma2(ull& d, ull a, ull b){
    asm("fma.rn.f32x2 %0, %1, %2, %0;" : "+l"(d) : "l"(a), "l"(b));
}
__device__ __forceinline__ float2 up2(ull v){
    unsigned lo, hi;
    asm("mov.b64 {%0, %1}, %2;" : "=r"(lo), "=r"(hi) : "l"(v));
    return make_float2(__uint_as_float(lo), __uint_as_float(hi));
}
__device__ __forceinline__ float lrelu(float v){ return v >= 0.f ? v : 0.01f*v; }

// ---- dynamic smem layout (floats) ----
// Xs  [2][16][128] @0      (4096)
// Ws2 [2][16][256] @4096   (8192)  -- W stored DUPLICATED: pair {v,v} per value
// aux @12288: wsm(128) + biasD(129)   (argmax kernel only)
#define SM_XS 0
#define SM_WS 4096
#define SM_AUX 12288
#define SM_FLOATS (12288 + 260)

// Core: one CTA computes a 128(O) x 128(W) tile for row h, K=128.
// X and W streamed from global in 8 chunks of 16 k, double-buffered.
// W is stored in smem pre-duplicated as {v,v} float2 pairs so the inner loop
// feeds LDS.128 results DIRECTLY into fma.rn.f32x2 (no pk2/MOV splat).
// Reads of Ws2 are broadcast within each 16-thread og-group -> conflict-free.
// If MASK: threads tid<128 also accumulate the 129th classifier row.
template<bool MASK>
__device__ __forceinline__ void gemm_core(
    const float* __restrict__ Xh, size_t xRS,
    const float* __restrict__ Wh,
    float* __restrict__ Ws2, float* __restrict__ Xs,
    ull (&acc)[8][4],
    const float* __restrict__ wsm, float* __restrict__ mAcc)
{
    const int tid = threadIdx.x;
    const int og = tid >> 4, wg = tid & 15;
    const int o0 = og << 3, t4 = wg << 2;
    const int xk = tid >> 4;            // Xs load: row within chunk (16 rows)
    const int xc = (tid & 15) << 2;     // Xs load: col base (2 float4 / thread)
    const int wq = tid & 3;             // Ws load: k-quad
    const int wo = tid >> 2;            // Ws load: o (0..63, +64)

    float4 xst0, xst1, wst0, wst1;

    // prologue: chunk 0
    xst0 = *reinterpret_cast<const float4*>(Xh + (size_t)xk * xRS + xc);
    xst1 = *reinterpret_cast<const float4*>(Xh + (size_t)xk * xRS + xc + 64);
    wst0 = *reinterpret_cast<const float4*>(Wh + wo*128 + wq*4);
    wst1 = *reinterpret_cast<const float4*>(Wh + (wo+64)*128 + wq*4);
    *reinterpret_cast<float4*>(&Xs[xk*128 + xc])      = xst0;
    *reinterpret_cast<float4*>(&Xs[xk*128 + xc + 64]) = xst1;
    {
        const float* s0 = &wst0.x; const float* s1 = &wst1.x;
        #pragma unroll
        for (int i = 0; i < 4; ++i){
            int k = wq*4 + i;
            *reinterpret_cast<float2*>(&Ws2[k*256 + 2*(wo ^ (wq<<3))]) =
                make_float2(s0[i], s0[i]);
            *reinterpret_cast<float2*>(&Ws2[k*256 + 2*((wo+64) ^ (wq<<3))]) =
                make_float2(s1[i], s1[i]);
        }
    }
    __syncthreads();

    int buf = 0;
    #pragma unroll 1
    for (int ch = 0; ch < 8; ++ch){
        if (ch < 7){
            int k0 = (ch+1)*16;
            xst0 = *reinterpret_cast<const float4*>(Xh + (size_t)(k0 + xk) * xRS + xc);
            xst1 = *reinterpret_cast<const float4*>(Xh + (size_t)(k0 + xk) * xRS + xc + 64);
            wst0 = *reinterpret_cast<const float4*>(Wh + wo*128 + k0 + wq*4);
            wst1 = *reinterpret_cast<const float4*>(Wh + (wo+64)*128 + k0 + wq*4);
        }
        const float* Wb = Ws2 + buf*4096;
        const float* Xc = Xs  + buf*2048;
        #pragma unroll
        for (int k = 0; k < 16; ++k){
            int wOff = ((k >> 2) & 3) << 3;
            // 8 duplicated pairs for o0..o0+7: contiguous 64B, broadcast read
            const ulonglong2* wr =
                reinterpret_cast<const ulonglong2*>(&Wb[k*256 + 2*(o0 ^ wOff)]);
            ulonglong2 wA = wr[0], wB = wr[1], wC = wr[2], wD = wr[3];
            ull wp[8] = {wA.x, wA.y, wB.x, wB.y, wC.x, wC.y, wD.x, wD.y};
            ulonglong2 v0 = *reinterpret_cast<const ulonglong2*>(&Xc[k*128 + t4]);
            ulonglong2 v1 = *reinterpret_cast<const ulonglong2*>(&Xc[k*128 + t4 + 64]);
            #pragma unroll
            for (int o = 0; o < 8; ++o){
                fma2(acc[o][0], v0.x, wp[o]);
                fma2(acc[o][1], v0.y, wp[o]);
                fma2(acc[o][2], v1.x, wp[o]);
                fma2(acc[o][3], v1.y, wp[o]);
            }
        }
        if (MASK && tid < 128){
            #pragma unroll
            for (int k = 0; k < 16; k += 2){
                mAcc[0] = fmaf(Xc[k*128 + tid],     wsm[ch*16 + k],     mAcc[0]);
                mAcc[1] = fmaf(Xc[(k+1)*128 + tid], wsm[ch*16 + k + 1], mAcc[1]);
            }
        }
        if (ch < 7){
            int nb = buf ^ 1;
            float* xd = Xs + nb*2048;
            float* wd = Ws2 + nb*4096;
            *reinterpret_cast<float4*>(&xd[xk*128 + xc])      = xst0;
            *reinterpret_cast<float4*>(&xd[xk*128 + xc + 64]) = xst1;
            const float* s0 = &wst0.x; const float* s1 = &wst1.x;
            #pragma unroll
            for (int i = 0; i < 4; ++i){
                int k = wq*4 + i;
                *reinterpret_cast<float2*>(&wd[k*256 + 2*(wo ^ (wq<<3))]) =
                    make_float2(s0[i], s0[i]);
                *reinterpret_cast<float2*>(&wd[k*256 + 2*((wo+64) ^ (wq<<3))]) =
                    make_float2(s1[i], s1[i]);
            }
            __syncthreads();
            buf = nb;
        }
    }
}

#define ZERO_ACC(acc) do { _Pragma("unroll") for(int o=0;o<8;o++){ _Pragma("unroll") for(int q=0;q<4;q++) (acc)[o][q]=0ull; } } while(0)

// GEMM + bias + leaky-relu. dual: blockIdx.x&1 selects weight set A/B
// (interleaved so both read the same X tile back-to-back -> L2 reuse).
// sel==1 with transB stores output TRANSPOSED as [h][w][o] (for k_final).
__global__ void __launch_bounds__(256, 2)
k_gemm_lrelu(const float* __restrict__ X, size_t xHS, size_t xRS,
             const float* __restrict__ WtA, const float* __restrict__ BtA, float* __restrict__ YA,
             const float* __restrict__ WtB, const float* __restrict__ BtB, float* __restrict__ YB,
             int dual, int transB)
{
    extern __shared__ float sm[];
    float* Xs  = sm + SM_XS;
    float* Ws2 = sm + SM_WS;

    int bx = blockIdx.x;
    int sel = 0, wTile;
    if (dual){ sel = bx & 1; wTile = bx >> 1; } else wTile = bx;
    const int h = blockIdx.y;
    const int wBase = wTile * 128;
    const float* Wt = sel ? WtB : WtA;
    const float* Bt = sel ? BtB : BtA;
    float* Y = sel ? YB : YA;

    ull acc[8][4];
    ZERO_ACC(acc);

    const float* Xh = X + (size_t)h*xHS + wBase;
    const float* Wh = Wt + (size_t)h*16384;
    float mDummy[2];
    gemm_core<false>(Xh, xRS, Wh, Ws2, Xs, acc, nullptr, mDummy);

    const int tid = threadIdx.x;
    const int og = tid>>4, wg = tid&15;
    const int o0 = og<<3, t4 = wg<<2;

    if (sel == 1 && transB){
        // transposed store: (o, w) -> Y[h*CHW + w*128 + o]
        #pragma unroll
        for (int half = 0; half < 2; ++half){
            #pragma unroll
            for (int i = 0; i < 4; ++i){
                int w = wBase + t4 + i + half*64;
                float vv[8];
                #pragma unroll
                for (int o = 0; o < 8; ++o){
                    float2 f2 = up2(acc[o][half*2 + (i>>1)]);
                    vv[o] = lrelu(((i & 1) ? f2.y : f2.x) + Bt[h*128 + o0 + o]);
                }
                float* dst = Y + (size_t)h*CHW + (size_t)w*128 + o0;
                *reinterpret_cast<float4*>(dst)     = make_float4(vv[0],vv[1],vv[2],vv[3]);
                *reinterpret_cast<float4*>(dst + 4) = make_float4(vv[4],vv[5],vv[6],vv[7]);
            }
        }
    } else {
        #pragma unroll
        for (int o = 0; o < 8; ++o){
            float bo = Bt[h*128 + o0 + o];
            float* yo = Y + (size_t)h*CHW + (size_t)(o0+o)*WW + wBase;
            float2 a0 = up2(acc[o][0]), a1 = up2(acc[o][1]);
            float2 a2 = up2(acc[o][2]), a3 = up2(acc[o][3]);
            *reinterpret_cast<float4*>(yo + t4) =
                make_float4(lrelu(a0.x+bo), lrelu(a0.y+bo), lrelu(a1.x+bo), lrelu(a1.y+bo));
            *reinterpret_cast<float4*>(yo + t4 + 64) =
                make_float4(lrelu(a2.x+bo), lrelu(a2.y+bo), lrelu(a3.x+bo), lrelu(a3.y+bo));
        }
    }
}

// Classifier GEMM (129-row weights) + fused mask row + fused in-CTA argmax.
// Tile covers all 128 classes x 128 cols -> logits never leave the CTA.
__global__ void __launch_bounds__(256, 2)
k_gemm_argmax(const float* __restrict__ X, const float* __restrict__ Wt,
              const float* __restrict__ Bt, int* __restrict__ inds,
              float* __restrict__ outMask)
{
    extern __shared__ float sm[];
    float* Xs   = sm + SM_XS;
    float* Ws2  = sm + SM_WS;
    float* wsm  = sm + SM_AUX;          // 128
    float* biasD = sm + SM_AUX + 128;   // 129

    const int wTile = blockIdx.x, h = blockIdx.y;
    const int wBase = wTile * 128;
    const int tid = threadIdx.x;

    if (tid < 128){
        wsm[tid] = Wt[(size_t)h*16512 + 128*128 + tid];
        biasD[tid] = Bt[h*129 + tid];
    }
    if (tid == 128) biasD[128] = Bt[h*129 + 128];
    // ordered by gemm_core's prologue __syncthreads

    ull acc[8][4];
    ZERO_ACC(acc);
    float mAcc[2] = {0.f, 0.f};

    const float* Xh = X + (size_t)h*CHW + wBase;
    const float* Wh = Wt + (size_t)h*16512;
    gemm_core<true>(Xh, (size_t)WW, Wh, Ws2, Xs, acc, wsm, mAcc);

    const int og = tid>>4, wg = tid&15;
    const int o0 = og<<3, t4 = wg<<2;

    // per-thread argmax over its 8 classes for its 8 w (ascending class order,
    // strict > keeps the first max like jnp.argmax)
    float bestv[8]; int besti[8];
    #pragma unroll
    for (int o = 0; o < 8; ++o){
        float bo = biasD[o0 + o];
        float2 p0 = up2(acc[o][0]), p1 = up2(acc[o][1]);
        float2 p2 = up2(acc[o][2]), p3 = up2(acc[o][3]);
        float vals[8] = {p0.x+bo, p0.y+bo, p1.x+bo, p1.y+bo,
                         p2.x+bo, p2.y+bo, p3.x+bo, p3.y+bo};
        #pragma unroll
        for (int j = 0; j < 8; ++j){
            if (o == 0){ bestv[j] = vals[j]; besti[j] = o0; }
            else if (vals[j] > bestv[j]){ bestv[j] = vals[j]; besti[j] = o0 + o; }
        }
    }
    __syncthreads();   // all FMA reads of Ws2 done; reuse it for the reduction
    float* rv = Ws2;                                  // [16 og][128 w]
    int*   ri = reinterpret_cast<int*>(Ws2 + 2048);   // [16 og][128 w]
    #pragma unroll
    for (int j = 0; j < 8; ++j){
        int w = (j < 4) ? (t4 + j) : (64 + t4 + j - 4);
        rv[og*128 + w] = bestv[j];
        ri[og*128 + w] = besti[j];
    }
    __syncthreads();
    if (tid < 128){
        float bv = rv[tid]; int bi = ri[tid];
        #pragma unroll
        for (int g = 1; g < 16; ++g){     // ascending class blocks: first max wins
            float v = rv[g*128 + tid];
            if (v > bv){ bv = v; bi = ri[g*128 + tid]; }
        }
        const int pg = h*WW + wBase + tid;
        inds[pg] = bi;
        outMask[pg] = lrelu(mAcc[0] + mAcc[1] + biasD[128]);
    }
}

// Final: gathered per-pixel 128->4->1 regressor, warp-cooperative,
// TWO pixels in flight per iteration (independent FMA/shuffle chains).
// Reproduces the reference's index scramble: rows use n = w*448 + h, while
// inds_r interprets the same flat n as (h2, w2i) on a (448,512) grid.
__global__ void __launch_bounds__(256)
k_final(const float* __restrict__ xrT, const int* __restrict__ inds,
        const float* __restrict__ w2, const float* __restrict__ b2,
        const float* __restrict__ w3, const float* __restrict__ b3,
        float* __restrict__ out)
{
    const int warp = (blockIdx.x * blockDim.x + threadIdx.x) >> 5;
    const int lane = threadIdx.x & 31;
    const int base = warp * 32;
    if (base >= HW) return;

    float res = 0.f;
    #pragma unroll 1
    for (int it = 0; it < 16; ++it){
        const int p0 = base + 2*it;
        const int h = p0 >> 9, w0 = p0 & 511;
        const int n0 = w0*HH + h, n1 = n0 + HH;
        const int j0 = (n0 >> 9)*128 + __ldg(&inds[n0]);
        const int j1 = (n1 >> 9)*128 + __ldg(&inds[n1]);

        const float4* wpA = reinterpret_cast<const float4*>(w2 + (size_t)j0*512);
        const float4* wpB = reinterpret_cast<const float4*>(w2 + (size_t)j1*512);
        const float*  xpA = xrT + (size_t)h*CHW + (size_t)w0*128;
        const float*  xpB = xpA + 128;

        float4 a = make_float4(0.f,0.f,0.f,0.f);
        float4 b = make_float4(0.f,0.f,0.f,0.f);
        #pragma unroll
        for (int r = 0; r < 4; ++r){
            int c = r*32 + lane;
            float  xa = __ldg(&xpA[c]);
            float  xb = __ldg(&xpB[c]);
            float4 wa = __ldg(&wpA[c]);
            float4 wb = __ldg(&wpB[c]);
            a.x = fmaf(xa, wa.x, a.x); b.x = fmaf(xb, wb.x, b.x);
            a.y = fmaf(xa, wa.y, a.y); b.y = fmaf(xb, wb.y, b.y);
            a.z = fmaf(xa, wa.z, a.z); b.z = fmaf(xb, wb.z, b.z);
            a.w = fmaf(xa, wa.w, a.w); b.w = fmaf(xb, wb.w, b.w);
        }
        #pragma unroll
        for (int s = 16; s > 0; s >>= 1){
            a.x += __shfl_xor_sync(0xffffffffu, a.x, s);
            b.x += __shfl_xor_sync(0xffffffffu, b.x, s);
            a.y += __shfl_xor_sync(0xffffffffu, a.y, s);
            b.y += __shfl_xor_sync(0xffffffffu, b.y, s);
            a.z += __shfl_xor_sync(0xffffffffu, a.z, s);
            b.z += __shfl_xor_sync(0xffffffffu, b.z, s);
            a.w += __shfl_xor_sync(0xffffffffu, a.w, s);
            b.w += __shfl_xor_sync(0xffffffffu, b.w, s);
        }
        if (lane == 2*it || lane == 2*it + 1){
            const bool odd = (lane & 1);
            const int  j   = odd ? j1 : j0;
            const float4 v = odd ? b : a;
            float4 bb  = *reinterpret_cast<const float4*>(b2 + 4*(size_t)j);
            float h0 = lrelu(v.x + bb.x), h1 = lrelu(v.y + bb.y);
            float h2 = lrelu(v.z + bb.z), h3 = lrelu(v.w + bb.w);
            float4 w3v = *reinterpret_cast<const float4*>(w3 + 4*(size_t)j);
            float r2 = b3[j];
            r2 = fmaf(h0, w3v.x, r2); r2 = fmaf(h1, w3v.y, r2);
            r2 = fmaf(h2, w3v.z, r2); r2 = fmaf(h3, w3v.w, r2);
            res = ((float)__ldg(&inds[base + lane]) + r2) * (1.0f/128.0f);
        }
    }
    out[base + lane] = res;   // coalesced store of the warp's 32 results
}

extern "C" void kernel_launch(void* const* d_in, const int* in_sizes, int n_in,
                              void* d_out, int out_size)
{
    (void)in_sizes; (void)n_in; (void)out_size;
    const float* x_in  = (const float*)d_in[0];
    const float* w_cl1 = (const float*)d_in[1];
    const float* b_cl1 = (const float*)d_in[2];
    const float* w_cl2 = (const float*)d_in[3];
    const float* b_cl2 = (const float*)d_in[4];
    const float* w_cl3 = (const float*)d_in[5];
    const float* b_cl3 = (const float*)d_in[6];
    const float* w_reg1= (const float*)d_in[7];
    const float* b_reg1= (const float*)d_in[8];
    const float* w2    = (const float*)d_in[9];
    const float* b2    = (const float*)d_in[10];
    const float* w3    = (const float*)d_in[11];
    const float* b3    = (const float*)d_in[12];
    float* out = (float*)d_out;

    float *t1, *t2, *xr; int* inds;
    cudaGetSymbolAddress((void**)&t1, g_t1);
    cudaGetSymbolAddress((void**)&t2, g_t2);
    cudaGetSymbolAddress((void**)&xr, g_xr);
    cudaGetSymbolAddress((void**)&inds, g_inds);

    const int smemB = SM_FLOATS * 4;   // ~50.2KB -> 2 CTAs/SM
    cudaFuncSetAttribute(k_gemm_lrelu, cudaFuncAttributeMaxDynamicSharedMemorySize, smemB);
    cudaFuncSetAttribute(k_gemm_argmax, cudaFuncAttributeMaxDynamicSharedMemorySize, smemB);

    // x_in[c][h][w]: per-h base stride 512, channel stride H*W
    // L1 dual: cl1 -> t1 [h][c][w]; reg1 -> xr TRANSPOSED [h][w][c]
    k_gemm_lrelu<<<dim3(8, HH), 256, smemB>>>(x_in, (size_t)WW, (size_t)HW,
                                              w_cl1, b_cl1, t1,
                                              w_reg1, b_reg1, xr, 1, 1);
    // L2: t1 -> t2
    k_gemm_lrelu<<<dim3(4, HH), 256, smemB>>>(t1, (size_t)CHW, (size_t)WW,
                                              w_cl2, b_cl2, t2,
                                              nullptr, nullptr, nullptr, 0, 0);
    // L3: t2 -> inds + mask (logits stay on-chip)
    k_gemm_argmax<<<dim3(4, HH), 256, smemB>>>(t2, w_cl3, b_cl3, inds, out + HW);
    // regressor -> out[0:HW)
    k_final<<<HW/32/8, 256>>>(xr, inds, w2, b2, w3, b3, out);
}

// round 17
// speedup vs baseline: 1.2150x; 1.2150x over previous
#include <cuda_runtime.h>
#include <cstdint>

#define HH 448
#define WW 512
#define HW (HH*WW)        // 229376
#define CHW 65536         // per-h plane: 128*512 ([c][w]) or 512*128 ([w][c])

typedef unsigned long long ull;

// scratch (allocation-free rule)
__device__ float g_t1[(size_t)HH*CHW];      // [h][c][w]
__device__ float g_t2[(size_t)HH*CHW];      // [h][c][w]
__device__ float g_xr[(size_t)HH*CHW];      // TRANSPOSED: [h][w][c]
__device__ int   g_inds[HW];

__device__ __forceinline__ ull pk2(float v){
    ull r; unsigned u = __float_as_uint(v);
    asm("mov.b64 %0, {%1, %1};" : "=l"(r) : "r"(u));
    return r;
}
__device__ __forceinline__ void fma2(ull& d, ull a, ull b){
    asm("fma.rn.f32x2 %0, %1, %2, %0;" : "+l"(d) : "l"(a), "l"(b));
}
__device__ __forceinline__ float2 up2(ull v){
    unsigned lo, hi;
    asm("mov.b64 {%0, %1}, %2;" : "=r"(lo), "=r"(hi) : "l"(v));
    return make_float2(__uint_as_float(lo), __uint_as_float(hi));
}
__device__ __forceinline__ float lrelu(float v){ return v >= 0.f ? v : 0.01f*v; }

// Core (R11-proven): one CTA computes a 128(O) x 128(W) tile for row h, K=128.
// X and W streamed from global in 8 chunks of 16 k, double-buffered, XOR
// swizzle on the W tile for conflict-free STS. acc[8][4] f32x2 pairs.
// If MASK: threads tid<128 also accumulate the 129th classifier row
// (mAcc partials, col = tid) from the resident X chunk.
template<bool MASK>
__device__ __forceinline__ void gemm_core(
    const float* __restrict__ Xh, size_t xRS,
    const float* __restrict__ Wh,
    float (&Ws)[2][16][128], float (&Xs)[2][16][128],
    ull (&acc)[8][4],
    const float* __restrict__ wsm, float* __restrict__ mAcc)
{
    const int tid = threadIdx.x;
    const int og = tid >> 4, wg = tid & 15;
    const int o0 = og << 3, t4 = wg << 2;
    const int xk = tid >> 4;            // Xs load: row within chunk (16 rows)
    const int xc = (tid & 15) << 2;     // Xs load: col base (2 float4 / thread)
    const int wq = tid & 3;             // Ws load: k-quad
    const int wo = tid >> 2;            // Ws load: o (0..63, +64)

    float4 xst0, xst1, wst0, wst1;

    // prologue: chunk 0
    xst0 = *reinterpret_cast<const float4*>(Xh + (size_t)xk * xRS + xc);
    xst1 = *reinterpret_cast<const float4*>(Xh + (size_t)xk * xRS + xc + 64);
    wst0 = *reinterpret_cast<const float4*>(Wh + wo*128 + wq*4);
    wst1 = *reinterpret_cast<const float4*>(Wh + (wo+64)*128 + wq*4);
    *reinterpret_cast<float4*>(&Xs[0][xk][xc])      = xst0;
    *reinterpret_cast<float4*>(&Xs[0][xk][xc + 64]) = xst1;
    {
        const float* s0 = &wst0.x; const float* s1 = &wst1.x;
        #pragma unroll
        for (int i = 0; i < 4; ++i){
            int k = wq*4 + i;
            Ws[0][k][wo ^ (wq<<3)] = s0[i];          // XOR swizzle: conflict-free
            Ws[0][k][(wo+64) ^ (wq<<3)] = s1[i];
        }
    }
    __syncthreads();

    int buf = 0;
    #pragma unroll 1
    for (int ch = 0; ch < 8; ++ch){
        if (ch < 7){
            int k0 = (ch+1)*16;
            xst0 = *reinterpret_cast<const float4*>(Xh + (size_t)(k0 + xk) * xRS + xc);
            xst1 = *reinterpret_cast<const float4*>(Xh + (size_t)(k0 + xk) * xRS + xc + 64);
            wst0 = *reinterpret_cast<const float4*>(Wh + wo*128 + k0 + wq*4);
            wst1 = *reinterpret_cast<const float4*>(Wh + (wo+64)*128 + k0 + wq*4);
        }
        #pragma unroll
        for (int k = 0; k < 16; ++k){
            int wOff = ((k >> 2) & 3) << 3;
            const float4* wr = reinterpret_cast<const float4*>(&Ws[buf][k][o0 ^ wOff]);
            float4 wa = wr[0], wb2 = wr[1];
            float wv[8] = {wa.x,wa.y,wa.z,wa.w,wb2.x,wb2.y,wb2.z,wb2.w};
            ulonglong2 v0 = *reinterpret_cast<const ulonglong2*>(&Xs[buf][k][t4]);
            ulonglong2 v1 = *reinterpret_cast<const ulonglong2*>(&Xs[buf][k][t4 + 64]);
            #pragma unroll
            for (int o = 0; o < 8; ++o){
                ull wp = pk2(wv[o]);
                fma2(acc[o][0], v0.x, wp);
                fma2(acc[o][1], v0.y, wp);
                fma2(acc[o][2], v1.x, wp);
                fma2(acc[o][3], v1.y, wp);
            }
        }
        if (MASK && tid < 128){
            #pragma unroll
            for (int k = 0; k < 16; k += 2){
                mAcc[0] = fmaf(Xs[buf][k][tid],   wsm[ch*16 + k],     mAcc[0]);
                mAcc[1] = fmaf(Xs[buf][k+1][tid], wsm[ch*16 + k + 1], mAcc[1]);
            }
        }
        if (ch < 7){
            int nb = buf ^ 1;
            *reinterpret_cast<float4*>(&Xs[nb][xk][xc])      = xst0;
            *reinterpret_cast<float4*>(&Xs[nb][xk][xc + 64]) = xst1;
            const float* s0 = &wst0.x; const float* s1 = &wst1.x;
            #pragma unroll
            for (int i = 0; i < 4; ++i){
                int k = wq*4 + i;
                Ws[nb][k][wo ^ (wq<<3)] = s0[i];
                Ws[nb][k][(wo+64) ^ (wq<<3)] = s1[i];
            }
            __syncthreads();
            buf = nb;
        }
    }
}

#define ZERO_ACC(acc) do { _Pragma("unroll") for(int o=0;o<8;o++){ _Pragma("unroll") for(int q=0;q<4;q++) (acc)[o][q]=0ull; } } while(0)

// GEMM + bias + leaky-relu. dual: blockIdx.x&1 selects weight set A/B
// (interleaved so both read the same X tile back-to-back -> L2 reuse).
// sel==1 with transB stores output TRANSPOSED as [h][w][o] (for k_final).
__global__ void __launch_bounds__(256, 2)
k_gemm_lrelu(const float* __restrict__ X, size_t xHS, size_t xRS,
             const float* __restrict__ WtA, const float* __restrict__ BtA, float* __restrict__ YA,
             const float* __restrict__ WtB, const float* __restrict__ BtB, float* __restrict__ YB,
             int dual, int transB)
{
    __shared__ __align__(16) float Ws[2][16][128];
    __shared__ __align__(16) float Xs[2][16][128];
    int bx = blockIdx.x;
    int sel = 0, wTile;
    if (dual){ sel = bx & 1; wTile = bx >> 1; } else wTile = bx;
    const int h = blockIdx.y;
    const int wBase = wTile * 128;
    const float* Wt = sel ? WtB : WtA;
    const float* Bt = sel ? BtB : BtA;
    float* Y = sel ? YB : YA;

    ull acc[8][4];
    ZERO_ACC(acc);

    const float* Xh = X + (size_t)h*xHS + wBase;
    const float* Wh = Wt + (size_t)h*16384;
    float mDummy[2];
    gemm_core<false>(Xh, xRS, Wh, Ws, Xs, acc, nullptr, mDummy);

    const int tid = threadIdx.x;
    const int og = tid>>4, wg = tid&15;
    const int o0 = og<<3, t4 = wg<<2;

    if (sel == 1 && transB){
        // transposed store: (o, w) -> Y[h*CHW + w*128 + o]
        #pragma unroll
        for (int half = 0; half < 2; ++half){
            #pragma unroll
            for (int i = 0; i < 4; ++i){
                int w = wBase + t4 + i + half*64;
                float vv[8];
                #pragma unroll
                for (int o = 0; o < 8; ++o){
                    float2 f2 = up2(acc[o][half*2 + (i>>1)]);
                    vv[o] = lrelu(((i & 1) ? f2.y : f2.x) + Bt[h*128 + o0 + o]);
                }
                float* dst = Y + (size_t)h*CHW + (size_t)w*128 + o0;
                *reinterpret_cast<float4*>(dst)     = make_float4(vv[0],vv[1],vv[2],vv[3]);
                *reinterpret_cast<float4*>(dst + 4) = make_float4(vv[4],vv[5],vv[6],vv[7]);
            }
        }
    } else {
        #pragma unroll
        for (int o = 0; o < 8; ++o){
            float bo = Bt[h*128 + o0 + o];
            float* yo = Y + (size_t)h*CHW + (size_t)(o0+o)*WW + wBase;
            float2 a0 = up2(acc[o][0]), a1 = up2(acc[o][1]);
            float2 a2 = up2(acc[o][2]), a3 = up2(acc[o][3]);
            *reinterpret_cast<float4*>(yo + t4) =
                make_float4(lrelu(a0.x+bo), lrelu(a0.y+bo), lrelu(a1.x+bo), lrelu(a1.y+bo));
            *reinterpret_cast<float4*>(yo + t4 + 64) =
                make_float4(lrelu(a2.x+bo), lrelu(a2.y+bo), lrelu(a3.x+bo), lrelu(a3.y+bo));
        }
    }
}

// Classifier GEMM (129-row weights) + fused mask row + fused in-CTA argmax.
// Tile covers all 128 classes x 128 cols -> logits never leave the CTA.
__global__ void __launch_bounds__(256, 2)
k_gemm_argmax(const float* __restrict__ X, const float* __restrict__ Wt,
              const float* __restrict__ Bt, int* __restrict__ inds,
              float* __restrict__ outMask)
{
    __shared__ __align__(16) float Ws[2][16][128];
    __shared__ __align__(16) float Xs[2][16][128];
    __shared__ float wsm[128];
    __shared__ float biasD[129];
    const int wTile = blockIdx.x, h = blockIdx.y;
    const int wBase = wTile * 128;
    const int tid = threadIdx.x;

    if (tid < 128){
        wsm[tid] = Wt[(size_t)h*16512 + 128*128 + tid];
        biasD[tid] = Bt[h*129 + tid];
    }
    if (tid == 128) biasD[128] = Bt[h*129 + 128];
    // ordered by gemm_core's prologue __syncthreads

    ull acc[8][4];
    ZERO_ACC(acc);
    float mAcc[2] = {0.f, 0.f};

    const float* Xh = X + (size_t)h*CHW + wBase;
    const float* Wh = Wt + (size_t)h*16512;
    gemm_core<true>(Xh, (size_t)WW, Wh, Ws, Xs, acc, wsm, mAcc);

    const int og = tid>>4, wg = tid&15;
    const int o0 = og<<3, t4 = wg<<2;

    // per-thread argmax over its 8 classes for its 8 w (ascending class order,
    // strict > keeps the first max like jnp.argmax)
    float bestv[8]; int besti[8];
    #pragma unroll
    for (int o = 0; o < 8; ++o){
        float bo = biasD[o0 + o];
        float2 p0 = up2(acc[o][0]), p1 = up2(acc[o][1]);
        float2 p2 = up2(acc[o][2]), p3 = up2(acc[o][3]);
        float vals[8] = {p0.x+bo, p0.y+bo, p1.x+bo, p1.y+bo,
                         p2.x+bo, p2.y+bo, p3.x+bo, p3.y+bo};
        #pragma unroll
        for (int j = 0; j < 8; ++j){
            if (o == 0){ bestv[j] = vals[j]; besti[j] = o0; }
            else if (vals[j] > bestv[j]){ bestv[j] = vals[j]; besti[j] = o0 + o; }
        }
    }
    __syncthreads();    // all FMA reads of Ws done; reuse it for the reduction
    float* rv = &Ws[0][0][0];                         // [16 og][128 w]
    int*   ri = reinterpret_cast<int*>(&Ws[1][0][0]); // [16 og][128 w]
    #pragma unroll
    for (int j = 0; j < 8; ++j){
        int w = (j < 4) ? (t4 + j) : (64 + t4 + j - 4);
        rv[og*128 + w] = bestv[j];
        ri[og*128 + w] = besti[j];
    }
    __syncthreads();
    if (tid < 128){
        float bv = rv[tid]; int bi = ri[tid];
        #pragma unroll
        for (int g = 1; g < 16; ++g){     // ascending class blocks: first max wins
            float v = rv[g*128 + tid];
            if (v > bv){ bv = v; bi = ri[g*128 + tid]; }
        }
        const int pg = h*WW + wBase + tid;
        inds[pg] = bi;
        outMask[pg] = lrelu(mAcc[0] + mAcc[1] + biasD[128]);
    }
}

// Final: gathered per-pixel 128->4->1 regressor, warp-cooperative,
// TWO pixels in flight per iteration (independent FMA/shuffle chains).
// Reproduces the reference's index scramble: rows use n = w*448 + h, while
// inds_r interprets the same flat n as (h2, w2i) on a (448,512) grid.
__global__ void __launch_bounds__(256)
k_final(const float* __restrict__ xrT, const int* __restrict__ inds,
        const float* __restrict__ w2, const float* __restrict__ b2,
        const float* __restrict__ w3, const float* __restrict__ b3,
        float* __restrict__ out)
{
    const int warp = (blockIdx.x * blockDim.x + threadIdx.x) >> 5;
    const int lane = threadIdx.x & 31;
    const int base = warp * 32;
    if (base >= HW) return;

    float res = 0.f;
    #pragma unroll 1
    for (int it = 0; it < 16; ++it){
        const int p0 = base + 2*it;
        const int h = p0 >> 9, w0 = p0 & 511;
        const int n0 = w0*HH + h, n1 = n0 + HH;
        const int j0 = (n0 >> 9)*128 + __ldg(&inds[n0]);
        const int j1 = (n1 >> 9)*128 + __ldg(&inds[n1]);

        const float4* wpA = reinterpret_cast<const float4*>(w2 + (size_t)j0*512);
        const float4* wpB = reinterpret_cast<const float4*>(w2 + (size_t)j1*512);
        const float*  xpA = xrT + (size_t)h*CHW + (size_t)w0*128;
        const float*  xpB = xpA + 128;

        float4 a = make_float4(0.f,0.f,0.f,0.f);
        float4 b = make_float4(0.f,0.f,0.f,0.f);
        #pragma unroll
        for (int r = 0; r < 4; ++r){
            int c = r*32 + lane;
            float  xa = __ldg(&xpA[c]);
            float  xb = __ldg(&xpB[c]);
            float4 wa = __ldg(&wpA[c]);
            float4 wb = __ldg(&wpB[c]);
            a.x = fmaf(xa, wa.x, a.x); b.x = fmaf(xb, wb.x, b.x);
            a.y = fmaf(xa, wa.y, a.y); b.y = fmaf(xb, wb.y, b.y);
            a.z = fmaf(xa, wa.z, a.z); b.z = fmaf(xb, wb.z, b.z);
            a.w = fmaf(xa, wa.w, a.w); b.w = fmaf(xb, wb.w, b.w);
        }
        #pragma unroll
        for (int s = 16; s > 0; s >>= 1){
            a.x += __shfl_xor_sync(0xffffffffu, a.x, s);
            b.x += __shfl_xor_sync(0xffffffffu, b.x, s);
            a.y += __shfl_xor_sync(0xffffffffu, a.y, s);
            b.y += __shfl_xor_sync(0xffffffffu, b.y, s);
            a.z += __shfl_xor_sync(0xffffffffu, a.z, s);
            b.z += __shfl_xor_sync(0xffffffffu, b.z, s);
            a.w += __shfl_xor_sync(0xffffffffu, a.w, s);
            b.w += __shfl_xor_sync(0xffffffffu, b.w, s);
        }
        if (lane == 2*it || lane == 2*it + 1){
            const bool odd = (lane & 1);
            const int  j   = odd ? j1 : j0;
            const float4 v = odd ? b : a;
            float4 bb  = *reinterpret_cast<const float4*>(b2 + 4*(size_t)j);
            float h0 = lrelu(v.x + bb.x), h1 = lrelu(v.y + bb.y);
            float h2 = lrelu(v.z + bb.z), h3 = lrelu(v.w + bb.w);
            float4 w3v = *reinterpret_cast<const float4*>(w3 + 4*(size_t)j);
            float r2 = b3[j];
            r2 = fmaf(h0, w3v.x, r2); r2 = fmaf(h1, w3v.y, r2);
            r2 = fmaf(h2, w3v.z, r2); r2 = fmaf(h3, w3v.w, r2);
            res = ((float)__ldg(&inds[base + lane]) + r2) * (1.0f/128.0f);
        }
    }
    out[base + lane] = res;   // coalesced store of the warp's 32 results
}

extern "C" void kernel_launch(void* const* d_in, const int* in_sizes, int n_in,
                              void* d_out, int out_size)
{
    (void)in_sizes; (void)n_in; (void)out_size;
    const float* x_in  = (const float*)d_in[0];
    const float* w_cl1 = (const float*)d_in[1];
    const float* b_cl1 = (const float*)d_in[2];
    const float* w_cl2 = (const float*)d_in[3];
    const float* b_cl2 = (const float*)d_in[4];
    const float* w_cl3 = (const float*)d_in[5];
    const float* b_cl3 = (const float*)d_in[6];
    const float* w_reg1= (const float*)d_in[7];
    const float* b_reg1= (const float*)d_in[8];
    const float* w2    = (const float*)d_in[9];
    const float* b2    = (const float*)d_in[10];
    const float* w3    = (const float*)d_in[11];
    const float* b3    = (const float*)d_in[12];
    float* out = (float*)d_out;

    float *t1, *t2, *xr; int* inds;
    cudaGetSymbolAddress((void**)&t1, g_t1);
    cudaGetSymbolAddress((void**)&t2, g_t2);
    cudaGetSymbolAddress((void**)&xr, g_xr);
    cudaGetSymbolAddress((void**)&inds, g_inds);

    // x_in[c][h][w]: per-h base stride 512, channel stride H*W
    // L1 dual: cl1 -> t1 [h][c][w]; reg1 -> xr TRANSPOSED [h][w][c]
    k_gemm_lrelu<<<dim3(8, HH), 256>>>(x_in, (size_t)WW, (size_t)HW,
                                       w_cl1, b_cl1, t1,
                                       w_reg1, b_reg1, xr, 1, 1);
    // L2: t1 -> t2
    k_gemm_lrelu<<<dim3(4, HH), 256>>>(t1, (size_t)CHW, (size_t)WW,
                                       w_cl2, b_cl2, t2,
                                       nullptr, nullptr, nullptr, 0, 0);
    // L3: t2 -> inds + mask (logits stay on-chip)
    k_gemm_argmax<<<dim3(4, HH), 256>>>(t2, w_cl3, b_cl3, inds, out + HW);
    // regressor -> out[0:HW)
    k_final<<<HW/32/8, 256>>>(xr, inds, w2, b2, w3, b3, out);
}